// round 2
// baseline (speedup 1.0000x reference)
#include <cuda_runtime.h>
#include <cuda_bf16.h>
#include <math.h>

#define AB 16
#define AN 577
#define ADIM 768
#define AH 12
#define AD 64
#define QKVD 768          // per-matrix width (H*D)
#define QKV3 2304
#define AM (AB*AN)        // 9232
#define TROWS 30
#define QT 32
#define KT 64
#define NKT 10            // ceil(577/64)
#define NQT 19            // ceil(577/32)
#define SROW 584          // padded S row

// ---------------- scratch (static device allocations — allowed) --------------
__device__ float g_qkv[(size_t)AM * QKV3];     // [b*n, 3*768]
__device__ float g_att[(size_t)AM * ADIM];     // attention out, [b*n, h*d]
__device__ unsigned char g_iv[AN * AN];
__device__ unsigned char g_ih[AN * AN];

// ---------------- relative position index tables -----------------------------
__global__ void relidx_kernel() {
    int idx = blockIdx.x * blockDim.x + threadIdx.x;
    if (idx >= AN * AN) return;
    int q = idx / AN, k = idx % AN;
    unsigned char iv = 0, ih = 0;
    if (q > 0 && k > 0) {
        int rq = q - 1, rk = k - 1;
        int dv = rk / 24 - rq / 24;
        int dh = rk % 24 - rq % 24;
        dv = max(-14, min(14, dv));
        dh = max(-14, min(14, dh));
        iv = (unsigned char)(dv + 15);
        ih = (unsigned char)(dh + 15);
    }
    g_iv[idx] = iv;
    g_ih[idx] = ih;
}

// ---------------- fp32 SGEMM: C[M,N] = A[M,K] @ B[N,K]^T (+bias) -------------
// 128x128x16 tile, 256 threads, 8x8 per thread.
__global__ __launch_bounds__(256, 2) void sgemm_nt_kernel(
    const float* __restrict__ A, const float* __restrict__ B,
    const float* __restrict__ bias, float* __restrict__ C,
    int M, int N, int K)
{
    __shared__ float As[16][128];
    __shared__ float Bs[16][128];
    int tid = threadIdx.x;
    int m0 = blockIdx.y * 128;
    int n0 = blockIdx.x * 128;
    int tx = tid & 15, ty = tid >> 4;

    float acc[8][8];
#pragma unroll
    for (int i = 0; i < 8; i++)
#pragma unroll
        for (int j = 0; j < 8; j++) acc[i][j] = 0.f;

    for (int k0 = 0; k0 < K; k0 += 16) {
#pragma unroll
        for (int i = 0; i < 2; i++) {
            int l = tid + i * 256;           // 0..511
            int r = l >> 2;                  // 0..127
            int c4 = (l & 3) << 2;           // 0,4,8,12
            float4 va = make_float4(0.f, 0.f, 0.f, 0.f);
            if (m0 + r < M) va = *(const float4*)(A + (size_t)(m0 + r) * K + k0 + c4);
            As[c4 + 0][r] = va.x; As[c4 + 1][r] = va.y;
            As[c4 + 2][r] = va.z; As[c4 + 3][r] = va.w;
            float4 vb = make_float4(0.f, 0.f, 0.f, 0.f);
            if (n0 + r < N) vb = *(const float4*)(B + (size_t)(n0 + r) * K + k0 + c4);
            Bs[c4 + 0][r] = vb.x; Bs[c4 + 1][r] = vb.y;
            Bs[c4 + 2][r] = vb.z; Bs[c4 + 3][r] = vb.w;
        }
        __syncthreads();
#pragma unroll
        for (int kk = 0; kk < 16; kk++) {
            float a[8], b[8];
            *(float4*)&a[0] = *(const float4*)&As[kk][ty * 8];
            *(float4*)&a[4] = *(const float4*)&As[kk][ty * 8 + 4];
            *(float4*)&b[0] = *(const float4*)&Bs[kk][tx * 8];
            *(float4*)&b[4] = *(const float4*)&Bs[kk][tx * 8 + 4];
#pragma unroll
            for (int i = 0; i < 8; i++)
#pragma unroll
                for (int j = 0; j < 8; j++)
                    acc[i][j] += a[i] * b[j];
        }
        __syncthreads();
    }

#pragma unroll
    for (int i = 0; i < 8; i++) {
        int gm = m0 + ty * 8 + i;
        if (gm < M) {
#pragma unroll
            for (int j4 = 0; j4 < 2; j4++) {
                int gn = n0 + tx * 8 + j4 * 4;
                float4 v;
                v.x = acc[i][j4 * 4 + 0];
                v.y = acc[i][j4 * 4 + 1];
                v.z = acc[i][j4 * 4 + 2];
                v.w = acc[i][j4 * 4 + 3];
                if (bias) {
                    v.x += bias[gn + 0]; v.y += bias[gn + 1];
                    v.z += bias[gn + 2]; v.w += bias[gn + 3];
                }
                *(float4*)(C + (size_t)gm * N + gn) = v;
            }
        }
    }
}

// ---------------- attention kernel -------------------------------------------
// One block = one (b,h) x 32-query tile. Two-pass softmax with S materialized
// in shared memory. Relative-position K bias via 30-entry per-row dot tables;
// relative-position V contribution via 30-bin histogram of P.
__global__ __launch_bounds__(256) void attn_kernel(
    const float* __restrict__ tab_kv, const float* __restrict__ tab_kh,
    const float* __restrict__ tab_vv, const float* __restrict__ tab_vh)
{
    extern __shared__ float sm[];
    float* sQ  = sm;                    // [32][64] pre-scaled Q
    float* sKV = sQ + QT * AD;          // [64][64] K (d-major) then V (k-major)
    float* sS  = sKV + KT * AD;         // [32][SROW]
    float* sQv = sS + QT * SROW;        // [32][30]
    float* sQh = sQv + QT * TROWS;      // [32][30]
    float* sWv = sQh + QT * TROWS;      // [32][32]
    float* sWh = sWv + QT * 32;         // [32][32]
    float* sL  = sWh + QT * 32;         // [32]

    int tid = threadIdx.x;
    int qt = blockIdx.x;
    int bh = blockIdx.y;
    int b = bh / AH, h = bh % AH;
    int q0 = qt * QT;
    const float scale = 0.125f;

    const float* qbase = g_qkv + (size_t)b * AN * QKV3 + h * AD;
    const float* kbase = qbase + QKVD;
    const float* vbase = qbase + 2 * QKVD;

    // ---- load Q (pre-scaled), zero bins ----
    for (int i = tid; i < QT * AD / 4; i += 256) {
        int r = i >> 4, d4 = (i & 15) << 2;
        int q = q0 + r;
        float4 v = make_float4(0.f, 0.f, 0.f, 0.f);
        if (q < AN) v = *(const float4*)(qbase + (size_t)q * QKV3 + d4);
        v.x *= scale; v.y *= scale; v.z *= scale; v.w *= scale;
        *(float4*)(sQ + r * AD + d4) = v;
    }
    for (int i = tid; i < QT * 32 * 2; i += 256) sWv[i] = 0.f;  // sWv+sWh contiguous
    __syncthreads();

    // ---- per-row 30-entry bias dot tables: qv[r][i] = (scale*q_r) . tab_kv[i] ----
    // NOTE: QT*TROWS = 960 work items; MUST grid-stride over 256 threads.
    for (int w = tid; w < QT * TROWS; w += 256) {
        int r = w / TROWS, i = w % TROWS;
        const float* qrow = sQ + r * AD;
        float av = 0.f, ah = 0.f;
#pragma unroll 8
        for (int d = 0; d < AD; d++) {
            float qd = qrow[d];
            av += qd * tab_kv[i * AD + d];
            ah += qd * tab_kh[i * AD + d];
        }
        sQv[r * TROWS + i] = av;
        sQh[r * TROWS + i] = ah;
    }

    // ---- pass 1: S = Qs @ K^T + bias ----
    int kg = tid & 31, qg = tid >> 5;   // 32 k-groups (x2 cols), 8 q-groups (x4 rows)
    for (int kt = 0; kt < NKT; kt++) {
        int k0 = kt * KT;
        __syncthreads();
        // load K transposed: sKV[d][c]
        {
            int c = tid & 63, ch = tid >> 6;  // ch: 4 chunks of 16 d's
            int k = k0 + c;
#pragma unroll
            for (int j = 0; j < 4; j++) {
                int d = ch * 16 + j * 4;
                float4 v = make_float4(0.f, 0.f, 0.f, 0.f);
                if (k < AN) v = *(const float4*)(kbase + (size_t)k * QKV3 + d);
                sKV[(d + 0) * KT + c] = v.x;
                sKV[(d + 1) * KT + c] = v.y;
                sKV[(d + 2) * KT + c] = v.z;
                sKV[(d + 3) * KT + c] = v.w;
            }
        }
        __syncthreads();
        float acc[4][2];
#pragma unroll
        for (int i = 0; i < 4; i++) { acc[i][0] = 0.f; acc[i][1] = 0.f; }
#pragma unroll 8
        for (int d = 0; d < AD; d++) {
            float2 bv = *(const float2*)(sKV + d * KT + kg * 2);
#pragma unroll
            for (int i = 0; i < 4; i++) {
                float a = sQ[(qg * 4 + i) * AD + d];
                acc[i][0] += a * bv.x;
                acc[i][1] += a * bv.y;
            }
        }
        // bias + store S
#pragma unroll
        for (int i = 0; i < 4; i++) {
            int r = qg * 4 + i;
            int q = min(q0 + r, AN - 1);
#pragma unroll
            for (int j = 0; j < 2; j++) {
                int c = kg * 2 + j;
                int k = k0 + c;
                if (k < AN) {
                    int iv = g_iv[q * AN + k];
                    int ih = g_ih[q * AN + k];
                    sS[r * SROW + k] = acc[i][j] + sQv[r * TROWS + iv] + sQh[r * TROWS + ih];
                }
            }
        }
    }
    __syncthreads();

    // ---- softmax + histogram binning ----
    {
        int r = tid >> 3, j = tid & 7;        // 8 threads per row
        int q = min(q0 + r, AN - 1);
        float mx = -1e30f;
        for (int k = j; k < AN; k += 8) mx = fmaxf(mx, sS[r * SROW + k]);
#pragma unroll
        for (int off = 4; off; off >>= 1) mx = fmaxf(mx, __shfl_xor_sync(0xffffffffu, mx, off));
        float sum = 0.f;
        for (int k = j; k < AN; k += 8) {
            float p = __expf(sS[r * SROW + k] - mx);
            sS[r * SROW + k] = p;
            sum += p;
            atomicAdd(&sWv[r * 32 + g_iv[q * AN + k]], p);
            atomicAdd(&sWh[r * 32 + g_ih[q * AN + k]], p);
        }
#pragma unroll
        for (int off = 4; off; off >>= 1) sum += __shfl_xor_sync(0xffffffffu, sum, off);
        if (j == 0) sL[r] = sum;
    }
    __syncthreads();

    // ---- pass 2: O = P @ V ----
    int tx = tid & 15, ty = tid >> 4;   // cols tx*4, rows ty*2
    float o[2][4];
#pragma unroll
    for (int i = 0; i < 2; i++)
#pragma unroll
        for (int j = 0; j < 4; j++) o[i][j] = 0.f;

    for (int kt = 0; kt < NKT; kt++) {
        int k0 = kt * KT;
        int kmax = min(KT, AN - k0);
        __syncthreads();
        for (int i = tid; i < KT * AD / 4; i += 256) {
            int kk = i >> 4, d4 = (i & 15) << 2;
            float4 v = make_float4(0.f, 0.f, 0.f, 0.f);
            if (k0 + kk < AN) v = *(const float4*)(vbase + (size_t)(k0 + kk) * QKV3 + d4);
            *(float4*)(sKV + kk * AD + d4) = v;
        }
        __syncthreads();
        for (int kk = 0; kk < kmax; kk++) {
            float4 vv = *(const float4*)(sKV + kk * AD + tx * 4);
            float p0 = sS[(ty * 2 + 0) * SROW + k0 + kk];
            float p1 = sS[(ty * 2 + 1) * SROW + k0 + kk];
            o[0][0] += p0 * vv.x; o[0][1] += p0 * vv.y;
            o[0][2] += p0 * vv.z; o[0][3] += p0 * vv.w;
            o[1][0] += p1 * vv.x; o[1][1] += p1 * vv.y;
            o[1][2] += p1 * vv.z; o[1][3] += p1 * vv.w;
        }
    }

    // ---- relative-V contribution: O += Wv@tab_vv + Wh@tab_vh ----
#pragma unroll 5
    for (int i = 0; i < TROWS; i++) {
        float4 tv = *(const float4*)(tab_vv + i * AD + tx * 4);
        float4 th = *(const float4*)(tab_vh + i * AD + tx * 4);
#pragma unroll
        for (int rr = 0; rr < 2; rr++) {
            float wv = sWv[(ty * 2 + rr) * 32 + i];
            float wh = sWh[(ty * 2 + rr) * 32 + i];
            o[rr][0] += wv * tv.x + wh * th.x;
            o[rr][1] += wv * tv.y + wh * th.y;
            o[rr][2] += wv * tv.z + wh * th.z;
            o[rr][3] += wv * tv.w + wh * th.w;
        }
    }

    // ---- normalize + store to [b, n, h*d] ----
#pragma unroll
    for (int rr = 0; rr < 2; rr++) {
        int r = ty * 2 + rr;
        int q = q0 + r;
        if (q < AN) {
            float inv = 1.f / sL[r];
            float4 res;
            res.x = o[rr][0] * inv; res.y = o[rr][1] * inv;
            res.z = o[rr][2] * inv; res.w = o[rr][3] * inv;
            *(float4*)(g_att + ((size_t)b * AN + q) * ADIM + h * AD + tx * 4) = res;
        }
    }
}

// ---------------- launcher ----------------------------------------------------
extern "C" void kernel_launch(void* const* d_in, const int* in_sizes, int n_in,
                              void* d_out, int out_size)
{
    const float* x      = (const float*)d_in[0];
    const float* qkv_w  = (const float*)d_in[1];
    const float* proj_w = (const float*)d_in[2];
    const float* proj_b = (const float*)d_in[3];
    const float* tab_kv = (const float*)d_in[4];
    const float* tab_kh = (const float*)d_in[5];
    const float* tab_vv = (const float*)d_in[6];
    const float* tab_vh = (const float*)d_in[7];
    float* out = (float*)d_out;

    float* qkv; cudaGetSymbolAddress((void**)&qkv, g_qkv);
    float* att; cudaGetSymbolAddress((void**)&att, g_att);

    // 1) relative-position index tables
    relidx_kernel<<<(AN * AN + 255) / 256, 256>>>();

    // 2) QKV projection: [9232,768] x [2304,768]^T
    {
        dim3 grid(QKV3 / 128, (AM + 127) / 128);
        sgemm_nt_kernel<<<grid, 256>>>(x, qkv_w, nullptr, qkv, AM, QKV3, ADIM);
    }

    // 3) attention
    {
        const int smem_bytes = (QT * AD + KT * AD + QT * SROW + 2 * QT * TROWS +
                                2 * QT * 32 + QT) * 4;
        cudaFuncSetAttribute(attn_kernel, cudaFuncAttributeMaxDynamicSharedMemorySize,
                             smem_bytes);
        dim3 grid(NQT, AB * AH);
        attn_kernel<<<grid, 256, smem_bytes>>>(tab_kv, tab_kh, tab_vv, tab_vh);
    }

    // 4) output projection: [9232,768] x [768,768]^T + bias
    {
        dim3 grid(ADIM / 128, (AM + 127) / 128);
        sgemm_nt_kernel<<<grid, 256>>>(att, proj_w, proj_b, out, AM, ADIM, ADIM);
    }
}

// round 4
// speedup vs baseline: 1.0352x; 1.0352x over previous
#include <cuda_runtime.h>
#include <cuda_bf16.h>
#include <math.h>

#define AB 16
#define AN 577
#define ADIM 768
#define AH 12
#define AD 64
#define QKVD 768          // per-matrix width (H*D)
#define QKV3 2304
#define AM (AB*AN)        // 9232
#define TROWS 30
#define QT2 64
#define NQT2 10           // ceil(577/64)

// ---------------- scratch (static device allocations — allowed) --------------
__device__ float g_qkv[(size_t)AM * QKV3];     // [b*n, 3*768]
__device__ float g_att[(size_t)AM * ADIM];     // attention out, [b*n, h*d]
__device__ unsigned short g_idx[AN * AN];      // iv | ih<<8

// ---------------- relative position index tables -----------------------------
__global__ void relidx_kernel() {
    int idx = blockIdx.x * blockDim.x + threadIdx.x;
    if (idx >= AN * AN) return;
    int q = idx / AN, k = idx % AN;
    int iv = 0, ih = 0;
    if (q > 0 && k > 0) {
        int rq = q - 1, rk = k - 1;
        int dv = rk / 24 - rq / 24;
        int dh = rk % 24 - rq % 24;
        dv = max(-14, min(14, dv));
        dh = max(-14, min(14, dh));
        iv = dv + 15;
        ih = dh + 15;
    }
    g_idx[idx] = (unsigned short)(iv | (ih << 8));
}

// ---------------- fp32 SGEMM: C[M,N] = A[M,K] @ B[N,K]^T (+bias) -------------
__global__ __launch_bounds__(256, 2) void sgemm_nt_kernel(
    const float* __restrict__ A, const float* __restrict__ B,
    const float* __restrict__ bias, float* __restrict__ C,
    int M, int N, int K)
{
    __shared__ float As[16][128];
    __shared__ float Bs[16][128];
    int tid = threadIdx.x;
    int m0 = blockIdx.y * 128;
    int n0 = blockIdx.x * 128;
    int tx = tid & 15, ty = tid >> 4;

    float acc[8][8];
#pragma unroll
    for (int i = 0; i < 8; i++)
#pragma unroll
        for (int j = 0; j < 8; j++) acc[i][j] = 0.f;

    for (int k0 = 0; k0 < K; k0 += 16) {
#pragma unroll
        for (int i = 0; i < 2; i++) {
            int l = tid + i * 256;
            int r = l >> 2;
            int c4 = (l & 3) << 2;
            float4 va = make_float4(0.f, 0.f, 0.f, 0.f);
            if (m0 + r < M) va = *(const float4*)(A + (size_t)(m0 + r) * K + k0 + c4);
            As[c4 + 0][r] = va.x; As[c4 + 1][r] = va.y;
            As[c4 + 2][r] = va.z; As[c4 + 3][r] = va.w;
            float4 vb = make_float4(0.f, 0.f, 0.f, 0.f);
            if (n0 + r < N) vb = *(const float4*)(B + (size_t)(n0 + r) * K + k0 + c4);
            Bs[c4 + 0][r] = vb.x; Bs[c4 + 1][r] = vb.y;
            Bs[c4 + 2][r] = vb.z; Bs[c4 + 3][r] = vb.w;
        }
        __syncthreads();
#pragma unroll
        for (int kk = 0; kk < 16; kk++) {
            float a[8], b[8];
            *(float4*)&a[0] = *(const float4*)&As[kk][ty * 8];
            *(float4*)&a[4] = *(const float4*)&As[kk][ty * 8 + 4];
            *(float4*)&b[0] = *(const float4*)&Bs[kk][tx * 8];
            *(float4*)&b[4] = *(const float4*)&Bs[kk][tx * 8 + 4];
#pragma unroll
            for (int i = 0; i < 8; i++)
#pragma unroll
                for (int j = 0; j < 8; j++)
                    acc[i][j] += a[i] * b[j];
        }
        __syncthreads();
    }

#pragma unroll
    for (int i = 0; i < 8; i++) {
        int gm = m0 + ty * 8 + i;
        if (gm < M) {
#pragma unroll
            for (int j4 = 0; j4 < 2; j4++) {
                int gn = n0 + tx * 8 + j4 * 4;
                float4 v;
                v.x = acc[i][j4 * 4 + 0];
                v.y = acc[i][j4 * 4 + 1];
                v.z = acc[i][j4 * 4 + 2];
                v.w = acc[i][j4 * 4 + 3];
                if (bias) {
                    v.x += bias[gn + 0]; v.y += bias[gn + 1];
                    v.z += bias[gn + 2]; v.w += bias[gn + 3];
                }
                *(float4*)(C + (size_t)gm * N + gn) = v;
            }
        }
    }
}

// ---------------- flash-style attention --------------------------------------
// One block = one (b,h) x 64-query tile, 256 threads (16x16), 4x4 per thread.
// Online softmax; rel-K bias via 30-entry per-row dot tables; rel-V via 30-bin
// running histograms (rescaled with the softmax max updates).
__global__ __launch_bounds__(256, 2) void attn_kernel(
    const float* __restrict__ tab_kv, const float* __restrict__ tab_kh,
    const float* __restrict__ tab_vv, const float* __restrict__ tab_vh)
{
    extern __shared__ float sm[];
    float* sQ  = sm;                    // [64][64]  pre-scaled Q
    float* sK  = sQ + 64 * 64;          // [64][68]  K^T (d-major, padded)
    float* sP  = sK + 64 * 68;          // [64][68]  P tile
    float* sV  = sP + 64 * 68;          // [64][64]  V (k-major)
    float* sW  = sV + 64 * 64;          // [64][64]  bins: [row][iv | 32+ih]
    float* sQv = sW + 64 * 64;          // [64][30]
    float* sQh = sQv + 64 * TROWS;      // [64][30]
    float* sM  = sQh + 64 * TROWS;      // [64]
    float* sL  = sM + 64;               // [64]

    const int tid = threadIdx.x;
    const int tx = tid & 15, ty = tid >> 4;
    const int row0 = ty * 4;
    const int bh = blockIdx.y;
    const int b = bh / AH, h = bh % AH;
    const int q0 = blockIdx.x * QT2;

    const float* qbase = g_qkv + (size_t)b * AN * QKV3 + h * AD;
    const float* kbase = qbase + QKVD;
    const float* vbase = qbase + 2 * QKVD;

    // ---- load Q (pre-scaled by 1/8) ----
    for (int i = tid; i < 64 * 16; i += 256) {
        int r = i >> 4, d4 = (i & 15) << 2;
        int q = min(q0 + r, AN - 1);
        float4 v = *(const float4*)(qbase + (size_t)q * QKV3 + d4);
        v.x *= 0.125f; v.y *= 0.125f; v.z *= 0.125f; v.w *= 0.125f;
        *(float4*)(sQ + r * 64 + d4) = v;
    }
    for (int i = tid; i < 64 * 64; i += 256) sW[i] = 0.f;
    if (tid < 64) { sM[tid] = -1e30f; sL[tid] = 0.f; }
    __syncthreads();

    // ---- per-row bias dot tables: qv[r][t] = (scale*q_r) . tab_kv[t] ----
    for (int w = tid; w < 64 * TROWS; w += 256) {
        int r = w / TROWS, t = w - r * TROWS;
        const float* qrow = sQ + r * 64;
        float av = 0.f, ah = 0.f;
#pragma unroll 16
        for (int d = 0; d < 64; d++) {
            float qd = qrow[d];
            av += qd * tab_kv[t * AD + d];
            ah += qd * tab_kh[t * AD + d];
        }
        sQv[r * TROWS + t] = av;
        sQh[r * TROWS + t] = ah;
    }

    int qc[4];
#pragma unroll
    for (int i = 0; i < 4; i++) qc[i] = min(q0 + row0 + i, AN - 1);

    float o[4][4];
#pragma unroll
    for (int i = 0; i < 4; i++)
#pragma unroll
        for (int j = 0; j < 4; j++) o[i][j] = 0.f;

    for (int kt = 0; kt < NQT2; kt++) {
        int k0 = kt * 64;
        __syncthreads();
        // ---- load K^T (clamped; invalid masked later) and V ----
        {
            int c = tid & 63, ch = tid >> 6;
            int k = min(k0 + c, AN - 1);
            const float* kr = kbase + (size_t)k * QKV3;
#pragma unroll
            for (int j = 0; j < 4; j++) {
                int d = ch * 16 + j * 4;
                float4 v = *(const float4*)(kr + d);
                sK[(d + 0) * 68 + c] = v.x;
                sK[(d + 1) * 68 + c] = v.y;
                sK[(d + 2) * 68 + c] = v.z;
                sK[(d + 3) * 68 + c] = v.w;
            }
        }
#pragma unroll
        for (int j = 0; j < 4; j++) {
            int idx = tid + j * 256;
            int kk = idx >> 4, d4 = (idx & 15) << 2;
            int k = k0 + kk;
            float4 v = make_float4(0.f, 0.f, 0.f, 0.f);
            if (k < AN) v = *(const float4*)(vbase + (size_t)k * QKV3 + d4);
            *(float4*)(sV + kk * 64 + d4) = v;
        }
        __syncthreads();

        // ---- S = Q K^T (4x4 per thread) ----
        float s[4][4];
#pragma unroll
        for (int i = 0; i < 4; i++)
#pragma unroll
            for (int j = 0; j < 4; j++) s[i][j] = 0.f;
#pragma unroll 4
        for (int d = 0; d < 64; d++) {
            float4 kv = *(const float4*)(sK + d * 68 + tx * 4);
#pragma unroll
            for (int i = 0; i < 4; i++) {
                float a = sQ[(row0 + i) * 64 + d];
                s[i][0] += a * kv.x; s[i][1] += a * kv.y;
                s[i][2] += a * kv.z; s[i][3] += a * kv.w;
            }
        }

        // ---- bias + mask ----
#pragma unroll
        for (int i = 0; i < 4; i++) {
            const unsigned short* ip = g_idx + qc[i] * AN;
            const float* qv = sQv + (row0 + i) * TROWS;
            const float* qh = sQh + (row0 + i) * TROWS;
#pragma unroll
            for (int j = 0; j < 4; j++) {
                int k = k0 + tx * 4 + j;
                if (k < AN) {
                    unsigned short e = ip[k];
                    s[i][j] += qv[e & 0xff] + qh[e >> 8];
                } else {
                    s[i][j] = -1e30f;
                }
            }
        }

        // ---- online softmax (per-row state in sM/sL, row group = 16 lanes) ----
        float mnew[4], f[4], rs[4];
#pragma unroll
        for (int i = 0; i < 4; i++) {
            float m = fmaxf(fmaxf(s[i][0], s[i][1]), fmaxf(s[i][2], s[i][3]));
#pragma unroll
            for (int off = 1; off < 16; off <<= 1)
                m = fmaxf(m, __shfl_xor_sync(0xffffffffu, m, off));
            float mold = sM[row0 + i];
            mnew[i] = fmaxf(mold, m);
            f[i] = __expf(mold - mnew[i]);
            float r = 0.f;
#pragma unroll
            for (int j = 0; j < 4; j++) {
                float p = __expf(s[i][j] - mnew[i]);
                s[i][j] = p;
                r += p;
            }
#pragma unroll
            for (int off = 1; off < 16; off <<= 1)
                r += __shfl_xor_sync(0xffffffffu, r, off);
            rs[i] = r;
        }
        __syncwarp();
        if (tx == 0) {
#pragma unroll
            for (int i = 0; i < 4; i++) {
                sM[row0 + i] = mnew[i];
                sL[row0 + i] = sL[row0 + i] * f[i] + rs[i];
            }
        }
        // ---- rescale bins (each lane owns 4 bin slots of its rows), then add ----
#pragma unroll
        for (int i = 0; i < 4; i++) {
            float* wrow = sW + (row0 + i) * 64 + tx * 4;
#pragma unroll
            for (int j = 0; j < 4; j++) wrow[j] *= f[i];
        }
        __syncwarp();
#pragma unroll
        for (int i = 0; i < 4; i++) {
            const unsigned short* ip = g_idx + qc[i] * AN;
            float* wrow = sW + (row0 + i) * 64;
#pragma unroll
            for (int j = 0; j < 4; j++) {
                int k = k0 + tx * 4 + j;
                if (k < AN) {
                    unsigned short e = ip[k];
                    atomicAdd(wrow + (e & 0xff), s[i][j]);
                    atomicAdd(wrow + 32 + (e >> 8), s[i][j]);
                }
            }
        }
        // ---- rescale O, publish P ----
#pragma unroll
        for (int i = 0; i < 4; i++) {
            o[i][0] *= f[i]; o[i][1] *= f[i]; o[i][2] *= f[i]; o[i][3] *= f[i];
            *(float4*)(sP + (row0 + i) * 68 + tx * 4) =
                make_float4(s[i][0], s[i][1], s[i][2], s[i][3]);
        }
        __syncthreads();

        // ---- O += P V ----
#pragma unroll 4
        for (int kk = 0; kk < 64; kk++) {
            float4 v = *(const float4*)(sV + kk * 64 + tx * 4);
#pragma unroll
            for (int i = 0; i < 4; i++) {
                float p = sP[(row0 + i) * 68 + kk];
                o[i][0] += p * v.x; o[i][1] += p * v.y;
                o[i][2] += p * v.z; o[i][3] += p * v.w;
            }
        }
    }
    __syncthreads();

    // ---- rel-V contribution: O += Wv@tab_vv + Wh@tab_vh ----
#pragma unroll 6
    for (int t = 0; t < TROWS; t++) {
        float4 tv = *(const float4*)(tab_vv + t * AD + tx * 4);
        float4 th = *(const float4*)(tab_vh + t * AD + tx * 4);
#pragma unroll
        for (int i = 0; i < 4; i++) {
            float wv = sW[(row0 + i) * 64 + t];
            float wh = sW[(row0 + i) * 64 + 32 + t];
            o[i][0] += wv * tv.x + wh * th.x;
            o[i][1] += wv * tv.y + wh * th.y;
            o[i][2] += wv * tv.z + wh * th.z;
            o[i][3] += wv * tv.w + wh * th.w;
        }
    }

    // ---- normalize + store ----
#pragma unroll
    for (int i = 0; i < 4; i++) {
        int q = q0 + row0 + i;
        if (q < AN) {
            float inv = 1.f / sL[row0 + i];
            float4 r;
            r.x = o[i][0] * inv; r.y = o[i][1] * inv;
            r.z = o[i][2] * inv; r.w = o[i][3] * inv;
            *(float4*)(g_att + ((size_t)b * AN + q) * ADIM + h * AD + tx * 4) = r;
        }
    }
}

// ---------------- launcher ----------------------------------------------------
extern "C" void kernel_launch(void* const* d_in, const int* in_sizes, int n_in,
                              void* d_out, int out_size)
{
    const float* x      = (const float*)d_in[0];
    const float* qkv_w  = (const float*)d_in[1];
    const float* proj_w = (const float*)d_in[2];
    const float* proj_b = (const float*)d_in[3];
    const float* tab_kv = (const float*)d_in[4];
    const float* tab_kh = (const float*)d_in[5];
    const float* tab_vv = (const float*)d_in[6];
    const float* tab_vh = (const float*)d_in[7];
    float* out = (float*)d_out;

    float* qkv; cudaGetSymbolAddress((void**)&qkv, g_qkv);
    float* att; cudaGetSymbolAddress((void**)&att, g_att);

    // 1) relative-position index table
    relidx_kernel<<<(AN * AN + 255) / 256, 256>>>();

    // 2) QKV projection: [9232,768] x [2304,768]^T
    {
        dim3 grid(QKV3 / 128, (AM + 127) / 128);
        sgemm_nt_kernel<<<grid, 256>>>(x, qkv_w, nullptr, qkv, AM, QKV3, ADIM);
    }

    // 3) attention
    {
        const int smem_floats = 64*64 + 64*68 + 64*68 + 64*64 + 64*64 +
                                2 * 64 * TROWS + 128;
        const int smem_bytes = smem_floats * 4;   // 83,840 B
        cudaFuncSetAttribute(attn_kernel, cudaFuncAttributeMaxDynamicSharedMemorySize,
                             smem_bytes);
        dim3 grid(NQT2, AB * AH);
        attn_kernel<<<grid, 256, smem_bytes>>>(tab_kv, tab_kh, tab_vv, tab_vh);
    }

    // 4) output projection: [9232,768] x [768,768]^T + bias
    {
        dim3 grid(ADIM / 128, (AM + 127) / 128);
        sgemm_nt_kernel<<<grid, 256>>>(att, proj_w, proj_b, out, AM, ADIM, ADIM);
    }
}

// round 5
// speedup vs baseline: 1.8189x; 1.7572x over previous
#include <cuda_runtime.h>
#include <cuda_bf16.h>
#include <math.h>

#define AB 16
#define AN 577
#define ADIM 768
#define AH 12
#define AD 64
#define QKVD 768          // per-matrix width (H*D)
#define QKV3 2304
#define AM (AB*AN)        // 9232
#define TROWS 30
#define QT2 64
#define NQT2 10           // ceil(577/64)

// ---------------- scratch (static device allocations — allowed) --------------
__device__ float g_qkv[(size_t)AM * QKV3];     // [b*n, 3*768]
__device__ float g_att[(size_t)AM * ADIM];     // attention out, [b*n, h*d]
__device__ unsigned short g_idx[AN * AN];      // iv | ih<<8

// ---------------- relative position index tables -----------------------------
__global__ void relidx_kernel() {
    int idx = blockIdx.x * blockDim.x + threadIdx.x;
    if (idx >= AN * AN) return;
    int q = idx / AN, k = idx % AN;
    int iv = 0, ih = 0;
    if (q > 0 && k > 0) {
        int rq = q - 1, rk = k - 1;
        int dv = rk / 24 - rq / 24;
        int dh = rk % 24 - rq % 24;
        dv = max(-14, min(14, dv));
        dh = max(-14, min(14, dh));
        iv = dv + 15;
        ih = dh + 15;
    }
    g_idx[idx] = (unsigned short)(iv | (ih << 8));
}

// ---------------- fp32 SGEMM: C[M,N] = A[M,K] @ B[N,K]^T (+bias) -------------
__global__ __launch_bounds__(256, 2) void sgemm_nt_kernel(
    const float* __restrict__ A, const float* __restrict__ B,
    const float* __restrict__ bias, float* __restrict__ C,
    int M, int N, int K)
{
    __shared__ float As[16][128];
    __shared__ float Bs[16][128];
    int tid = threadIdx.x;
    int m0 = blockIdx.y * 128;
    int n0 = blockIdx.x * 128;
    int tx = tid & 15, ty = tid >> 4;

    float acc[8][8];
#pragma unroll
    for (int i = 0; i < 8; i++)
#pragma unroll
        for (int j = 0; j < 8; j++) acc[i][j] = 0.f;

    for (int k0 = 0; k0 < K; k0 += 16) {
#pragma unroll
        for (int i = 0; i < 2; i++) {
            int l = tid + i * 256;
            int r = l >> 2;
            int c4 = (l & 3) << 2;
            float4 va = make_float4(0.f, 0.f, 0.f, 0.f);
            if (m0 + r < M) va = *(const float4*)(A + (size_t)(m0 + r) * K + k0 + c4);
            As[c4 + 0][r] = va.x; As[c4 + 1][r] = va.y;
            As[c4 + 2][r] = va.z; As[c4 + 3][r] = va.w;
            float4 vb = make_float4(0.f, 0.f, 0.f, 0.f);
            if (n0 + r < N) vb = *(const float4*)(B + (size_t)(n0 + r) * K + k0 + c4);
            Bs[c4 + 0][r] = vb.x; Bs[c4 + 1][r] = vb.y;
            Bs[c4 + 2][r] = vb.z; Bs[c4 + 3][r] = vb.w;
        }
        __syncthreads();
#pragma unroll
        for (int kk = 0; kk < 16; kk++) {
            float a[8], b[8];
            *(float4*)&a[0] = *(const float4*)&As[kk][ty * 8];
            *(float4*)&a[4] = *(const float4*)&As[kk][ty * 8 + 4];
            *(float4*)&b[0] = *(const float4*)&Bs[kk][tx * 8];
            *(float4*)&b[4] = *(const float4*)&Bs[kk][tx * 8 + 4];
#pragma unroll
            for (int i = 0; i < 8; i++)
#pragma unroll
                for (int j = 0; j < 8; j++)
                    acc[i][j] += a[i] * b[j];
        }
        __syncthreads();
    }

#pragma unroll
    for (int i = 0; i < 8; i++) {
        int gm = m0 + ty * 8 + i;
        if (gm < M) {
#pragma unroll
            for (int j4 = 0; j4 < 2; j4++) {
                int gn = n0 + tx * 8 + j4 * 4;
                float4 v;
                v.x = acc[i][j4 * 4 + 0];
                v.y = acc[i][j4 * 4 + 1];
                v.z = acc[i][j4 * 4 + 2];
                v.w = acc[i][j4 * 4 + 3];
                if (bias) {
                    v.x += bias[gn + 0]; v.y += bias[gn + 1];
                    v.z += bias[gn + 2]; v.w += bias[gn + 3];
                }
                *(float4*)(C + (size_t)gm * N + gn) = v;
            }
        }
    }
}

// ---------------- flash-style attention, 512 threads, 2x4 tiles --------------
// One block = one (b,h) x 64-query tile. Thread (tx, ry) owns rows ry*2,ry*2+1
// and cols tx*4..tx*4+3. Online softmax; rel-K bias via 30-entry per-row dot
// tables; rel-V via per-row 30-bin running histograms (run-merged atomics).
__global__ __launch_bounds__(512, 2) void attn_kernel(
    const float* __restrict__ tab_kv, const float* __restrict__ tab_kh,
    const float* __restrict__ tab_vv, const float* __restrict__ tab_vh)
{
    extern __shared__ float sm[];
    float* sQ  = sm;                    // [64][64]
    float* sK  = sQ + 64 * 64;          // [64 d][68] K^T; pre-loop: tab stage [60][65]
    float* sV  = sK + 64 * 68;          // [64 k][64]
    float* sP  = sV + 64 * 64;          // [64 r][68]
    float* sW  = sP + 64 * 68;          // [64 r][64] bins: [iv | 32+ih]
    float* sQv = sW + 64 * 64;          // [64][30]
    float* sQh = sQv + 64 * TROWS;      // [64][30]
    float* sM  = sQh + 64 * TROWS;      // [64]
    float* sL  = sM + 64;               // [64]

    const int tid = threadIdx.x;
    const int tx = tid & 15;
    const int ry = tid >> 4;            // 0..31
    const int r0 = ry * 2;
    const int bh = blockIdx.y;
    const int b = bh / AH, h = bh % AH;
    const int q0 = blockIdx.x * QT2;

    const float* qbase = g_qkv + (size_t)b * AN * QKV3 + h * AD;
    const float* kbase = qbase + QKVD;
    const float* vbase = qbase + 2 * QKVD;

    // ---- load Q (pre-scaled by 1/8); stage bias tables into sK region ----
#pragma unroll
    for (int p = 0; p < 2; p++) {
        int idx = tid + p * 512;
        int r = idx >> 4, d4 = (idx & 15) << 2;
        int q = min(q0 + r, AN - 1);
        float4 v = *(const float4*)(qbase + (size_t)q * QKV3 + d4);
        v.x *= 0.125f; v.y *= 0.125f; v.z *= 0.125f; v.w *= 0.125f;
        *(float4*)(sQ + r * 64 + d4) = v;
    }
    for (int w = tid; w < 60 * 64; w += 512) {     // tab stage, stride 65
        int t = w >> 6, d = w & 63;
        float val = (t < 30) ? tab_kv[t * 64 + d] : tab_kh[(t - 30) * 64 + d];
        sK[t * 65 + d] = val;
    }
    for (int i = tid; i < 64 * 64; i += 512) sW[i] = 0.f;
    if (tid < 64) { sM[tid] = -1e30f; sL[tid] = 0.f; }
    __syncthreads();

    // ---- per-row bias dot tables: qv[r][t] = (scale*q_r) . tab_kv[t] ----
    for (int w = tid; w < 64 * TROWS; w += 512) {
        int t = w % TROWS, r = w / TROWS;
        const float* qrow = sQ + r * 64;
        const float* tv = sK + t * 65;
        const float* th = sK + (t + 30) * 65;
        float av = 0.f, ah = 0.f;
#pragma unroll 16
        for (int d = 0; d < 64; d++) {
            float qd = qrow[d];
            av += qd * tv[d];
            ah += qd * th[d];
        }
        sQv[r * TROWS + t] = av;
        sQh[r * TROWS + t] = ah;
    }

    const int qc0 = min(q0 + r0, AN - 1);
    const int qc1 = min(q0 + r0 + 1, AN - 1);

    float o[2][4];
#pragma unroll
    for (int i = 0; i < 2; i++)
#pragma unroll
        for (int j = 0; j < 4; j++) o[i][j] = 0.f;

    for (int kt = 0; kt < NQT2; kt++) {
        int k0 = kt * 64;
        __syncthreads();   // protects sK (tabs / previous K) and sV reuse
        // ---- load K^T (clamped) and V (zero-padded) ----
        {
            int c = tid & 63, ch = tid >> 6;     // ch: 0..7, 8 d's each
            int k = min(k0 + c, AN - 1);
            const float* kr = kbase + (size_t)k * QKV3;
#pragma unroll
            for (int j = 0; j < 2; j++) {
                int d = ch * 8 + j * 4;
                float4 v = *(const float4*)(kr + d);
                sK[(d + 0) * 68 + c] = v.x;
                sK[(d + 1) * 68 + c] = v.y;
                sK[(d + 2) * 68 + c] = v.z;
                sK[(d + 3) * 68 + c] = v.w;
            }
        }
#pragma unroll
        for (int p = 0; p < 2; p++) {
            int idx = tid + p * 512;
            int kk = idx >> 4, d4 = (idx & 15) << 2;
            int k = k0 + kk;
            float4 v = make_float4(0.f, 0.f, 0.f, 0.f);
            if (k < AN) v = *(const float4*)(vbase + (size_t)k * QKV3 + d4);
            *(float4*)(sV + kk * 64 + d4) = v;
        }
        __syncthreads();

        // ---- S = Q K^T (2x4 per thread) ----
        float s[2][4];
#pragma unroll
        for (int i = 0; i < 2; i++)
#pragma unroll
            for (int j = 0; j < 4; j++) s[i][j] = 0.f;
#pragma unroll 8
        for (int d = 0; d < 64; d++) {
            float4 kv = *(const float4*)(sK + d * 68 + tx * 4);
            float a0 = sQ[r0 * 64 + d];
            float a1 = sQ[(r0 + 1) * 64 + d];
            s[0][0] += a0 * kv.x; s[0][1] += a0 * kv.y;
            s[0][2] += a0 * kv.z; s[0][3] += a0 * kv.w;
            s[1][0] += a1 * kv.x; s[1][1] += a1 * kv.y;
            s[1][2] += a1 * kv.z; s[1][3] += a1 * kv.w;
        }

        // ---- bias + mask ----
#pragma unroll
        for (int i = 0; i < 2; i++) {
            int q = i ? qc1 : qc0;
            const unsigned short* ip = g_idx + q * AN;
            const float* qv = sQv + (r0 + i) * TROWS;
            const float* qh = sQh + (r0 + i) * TROWS;
#pragma unroll
            for (int j = 0; j < 4; j++) {
                int k = k0 + tx * 4 + j;
                unsigned short e = ip[min(k, AN - 1)];
                if (k < AN) s[i][j] += qv[e & 0xff] + qh[e >> 8];
                else        s[i][j] = -1e30f;
            }
        }

        // ---- online softmax (16-lane row groups) ----
        float f[2], mnew[2], rs[2];
#pragma unroll
        for (int i = 0; i < 2; i++) {
            float m = fmaxf(fmaxf(s[i][0], s[i][1]), fmaxf(s[i][2], s[i][3]));
#pragma unroll
            for (int off = 1; off < 16; off <<= 1)
                m = fmaxf(m, __shfl_xor_sync(0xffffffffu, m, off));
            float mold = sM[r0 + i];
            float mn = fmaxf(mold, m);
            f[i] = __expf(mold - mn);
            float r = 0.f;
#pragma unroll
            for (int j = 0; j < 4; j++) {
                float p = __expf(s[i][j] - mn);
                s[i][j] = p;
                r += p;
            }
#pragma unroll
            for (int off = 1; off < 16; off <<= 1)
                r += __shfl_xor_sync(0xffffffffu, r, off);
            mnew[i] = mn; rs[i] = r;
        }
        __syncwarp();
        if (tx == 0) {
#pragma unroll
            for (int i = 0; i < 2; i++) {
                sM[r0 + i] = mnew[i];
                sL[r0 + i] = sL[r0 + i] * f[i] + rs[i];
            }
        }
        // ---- rescale O + bins; publish P ----
#pragma unroll
        for (int i = 0; i < 2; i++) {
            o[i][0] *= f[i]; o[i][1] *= f[i]; o[i][2] *= f[i]; o[i][3] *= f[i];
            float* wr = sW + (r0 + i) * 64 + tx * 4;
            wr[0] *= f[i]; wr[1] *= f[i]; wr[2] *= f[i]; wr[3] *= f[i];
            *(float4*)(sP + (r0 + i) * 68 + tx * 4) =
                make_float4(s[i][0], s[i][1], s[i][2], s[i][3]);
        }
        __syncwarp();
        // ---- histogram atomics (masked p's are exactly 0 -> safe) ----
#pragma unroll
        for (int i = 0; i < 2; i++) {
            int q = i ? qc1 : qc0;
            const unsigned short* ip = g_idx + q * AN;
            float* wr = sW + (r0 + i) * 64;
            int kb = k0 + tx * 4;
            unsigned short e0 = ip[min(kb + 0, AN - 1)];
            unsigned short e1 = ip[min(kb + 1, AN - 1)];
            unsigned short e2 = ip[min(kb + 2, AN - 1)];
            unsigned short e3 = ip[min(kb + 3, AN - 1)];
            // iv with run-merging (consecutive k mostly share iv)
            int cur = e0 & 0xff;
            float run = s[i][0];
            int v1 = e1 & 0xff, v2 = e2 & 0xff, v3 = e3 & 0xff;
            if (v1 == cur) run += s[i][1];
            else { atomicAdd(wr + cur, run); cur = v1; run = s[i][1]; }
            if (v2 == cur) run += s[i][2];
            else { atomicAdd(wr + cur, run); cur = v2; run = s[i][2]; }
            if (v3 == cur) run += s[i][3];
            else { atomicAdd(wr + cur, run); cur = v3; run = s[i][3]; }
            atomicAdd(wr + cur, run);
            // ih: 4 adds (consecutive k -> mostly distinct bins)
            atomicAdd(wr + 32 + (e0 >> 8), s[i][0]);
            atomicAdd(wr + 32 + (e1 >> 8), s[i][1]);
            atomicAdd(wr + 32 + (e2 >> 8), s[i][2]);
            atomicAdd(wr + 32 + (e3 >> 8), s[i][3]);
        }

        // ---- O += P V ----
#pragma unroll 8
        for (int kk = 0; kk < 64; kk++) {
            float4 v = *(const float4*)(sV + kk * 64 + tx * 4);
            float p0 = sP[r0 * 68 + kk];
            float p1 = sP[(r0 + 1) * 68 + kk];
            o[0][0] += p0 * v.x; o[0][1] += p0 * v.y;
            o[0][2] += p0 * v.z; o[0][3] += p0 * v.w;
            o[1][0] += p1 * v.x; o[1][1] += p1 * v.y;
            o[1][2] += p1 * v.z; o[1][3] += p1 * v.w;
        }
    }
    __syncthreads();

    // ---- rel-V contribution: O += Wv@tab_vv + Wh@tab_vh ----
#pragma unroll 6
    for (int t = 0; t < TROWS; t++) {
        float4 tv = *(const float4*)(tab_vv + t * AD + tx * 4);
        float4 th = *(const float4*)(tab_vh + t * AD + tx * 4);
#pragma unroll
        for (int i = 0; i < 2; i++) {
            float wv = sW[(r0 + i) * 64 + t];
            float wh = sW[(r0 + i) * 64 + 32 + t];
            o[i][0] += wv * tv.x + wh * th.x;
            o[i][1] += wv * tv.y + wh * th.y;
            o[i][2] += wv * tv.z + wh * th.z;
            o[i][3] += wv * tv.w + wh * th.w;
        }
    }

    // ---- normalize + store ----
#pragma unroll
    for (int i = 0; i < 2; i++) {
        int q = q0 + r0 + i;
        if (q < AN) {
            float inv = 1.f / sL[r0 + i];
            float4 r;
            r.x = o[i][0] * inv; r.y = o[i][1] * inv;
            r.z = o[i][2] * inv; r.w = o[i][3] * inv;
            *(float4*)(g_att + ((size_t)b * AN + q) * ADIM + h * AD + tx * 4) = r;
        }
    }
}

// ---------------- launcher ----------------------------------------------------
extern "C" void kernel_launch(void* const* d_in, const int* in_sizes, int n_in,
                              void* d_out, int out_size)
{
    const float* x      = (const float*)d_in[0];
    const float* qkv_w  = (const float*)d_in[1];
    const float* proj_w = (const float*)d_in[2];
    const float* proj_b = (const float*)d_in[3];
    const float* tab_kv = (const float*)d_in[4];
    const float* tab_kh = (const float*)d_in[5];
    const float* tab_vv = (const float*)d_in[6];
    const float* tab_vh = (const float*)d_in[7];
    float* out = (float*)d_out;

    float* qkv; cudaGetSymbolAddress((void**)&qkv, g_qkv);
    float* att; cudaGetSymbolAddress((void**)&att, g_att);

    // 1) relative-position index table
    relidx_kernel<<<(AN * AN + 255) / 256, 256>>>();

    // 2) QKV projection: [9232,768] x [2304,768]^T
    {
        dim3 grid(QKV3 / 128, (AM + 127) / 128);
        sgemm_nt_kernel<<<grid, 256>>>(x, qkv_w, nullptr, qkv, AM, QKV3, ADIM);
    }

    // 3) attention
    {
        const int smem_floats = 64*64 + 64*68 + 64*64 + 64*68 + 64*64 +
                                2 * 64 * TROWS + 128;
        const int smem_bytes = smem_floats * 4;   // 99,840 B
        cudaFuncSetAttribute(attn_kernel, cudaFuncAttributeMaxDynamicSharedMemorySize,
                             smem_bytes);
        dim3 grid(NQT2, AB * AH);
        attn_kernel<<<grid, 512, smem_bytes>>>(tab_kv, tab_kh, tab_vv, tab_vh);
    }

    // 4) output projection: [9232,768] x [768,768]^T + bias
    {
        dim3 grid(ADIM / 128, (AM + 127) / 128);
        sgemm_nt_kernel<<<grid, 256>>>(att, proj_w, proj_b, out, AM, ADIM, ADIM);
    }
}